// round 5
// baseline (speedup 1.0000x reference)
#include <cuda_runtime.h>
#include <cuda_bf16.h>
#include <cstdint>

#define BATCH 2
#define SEQ   2048
#define DM    1024
#define DS    16
#define MTOT  (BATCH*SEQ)   // 4096
#define CH    16            // scan chunks
#define CS    (SEQ/CH)      // 128 steps per chunk

// ----------------------------- scratch globals -----------------------------
__device__ float g_delta [MTOT*DM];       // (b,l,d)
__device__ float g_deltaT[BATCH*DM*SEQ];  // (b,d,l)
__device__ float g_xT    [BATCH*DM*SEQ];  // (b,d,l)
__device__ float g_B     [MTOT*DS];       // (b,l,n)
__device__ float g_C     [MTOT*DS];       // (b,l,n)
__device__ float g_yT    [BATCH*DM*SEQ];  // (b,d,l)
__device__ float g_P     [BATCH*DM*CH*DS];
__device__ float g_q     [BATCH*DM*CH*DS];
__device__ float g_h0    [BATCH*DM*CH*DS];
__device__ __nv_bfloat16 g_Xhi[MTOT*DM];
__device__ __nv_bfloat16 g_Xlo[MTOT*DM];
__device__ __nv_bfloat16 g_Whi[DM*DM];
__device__ __nv_bfloat16 g_Wlo[DM*DM];
__device__ __nv_bfloat16 g_Wbch[32*DM];   // [W_B ; W_C] hi
__device__ __nv_bfloat16 g_Wbcl[32*DM];   // [W_B ; W_C] lo

__device__ __forceinline__ float softplus_f(float z) {
    return fmaxf(z, 0.f) + log1pf(expf(-fabsf(z)));
}

__device__ __forceinline__ uint32_t smem_u32(const void* p) {
    uint32_t a;
    asm("{ .reg .u64 t; cvta.to.shared.u64 t, %1; cvt.u32.u64 %0, t; }"
        : "=r"(a) : "l"(p));
    return a;
}

#define CP16(dst, src) \
    asm volatile("cp.async.cg.shared.global [%0], [%1], 16;" :: "r"(dst), "l"(src))
#define CP_COMMIT() asm volatile("cp.async.commit_group;" ::: "memory")
#define CP_WAIT1()  asm volatile("cp.async.wait_group 1;" ::: "memory")

#define LDSM4(r, addr) \
    asm volatile("ldmatrix.sync.aligned.m8n8.x4.shared.b16 {%0,%1,%2,%3}, [%4];" \
        : "=r"((r)[0]), "=r"((r)[1]), "=r"((r)[2]), "=r"((r)[3]) : "r"(addr))

#define MMA16816(d, a, b0, b1) \
    asm volatile("mma.sync.aligned.m16n8k16.row.col.f32.bf16.bf16.f32 " \
        "{%0,%1,%2,%3}, {%4,%5,%6,%7}, {%8,%9}, {%0,%1,%2,%3};" \
        : "+f"((d)[0]), "+f"((d)[1]), "+f"((d)[2]), "+f"((d)[3]) \
        : "r"((a)[0]), "r"((a)[1]), "r"((a)[2]), "r"((a)[3]), "r"(b0), "r"(b1))

// ---------------------------------------------------------------------------
// Prep kernels
// ---------------------------------------------------------------------------
__device__ __forceinline__ void split1(float v, __nv_bfloat16& H, __nv_bfloat16& L) {
    H = __float2bfloat16_rn(v);
    L = __float2bfloat16_rn(v - __bfloat162float(H));
}

// split x AND transpose x -> g_xT in one pass. grid (DM/32, SEQ/32, BATCH), blk (32,8)
__global__ void split_x_t_kernel(const float* __restrict__ x) {
    __shared__ float t[32][33];
    const int b  = blockIdx.z;
    const int d0 = blockIdx.x * 32;
    const int l0 = blockIdx.y * 32;
    const int tx = threadIdx.x, ty = threadIdx.y;
#pragma unroll
    for (int i = 0; i < 32; i += 8) {
        const size_t src = ((size_t)(b * SEQ + l0 + ty + i)) * DM + d0 + tx;
        float v = x[src];
        t[ty + i][tx] = v;
        __nv_bfloat16 H, L; split1(v, H, L);
        g_Xhi[src] = H;
        g_Xlo[src] = L;
    }
    __syncthreads();
#pragma unroll
    for (int i = 0; i < 32; i += 8)
        g_xT[((size_t)(b * DM + d0 + ty + i)) * SEQ + l0 + tx] = t[tx][ty + i];
}

__global__ void split_w_kernel(const float* __restrict__ src) {
    int i = blockIdx.x * 256 + threadIdx.x;
    float4 v = ((const float4*)src)[i];
    ushort4 H, L;
    __nv_bfloat16 h, l;
    split1(v.x, h, l); H.x = __bfloat16_as_ushort(h); L.x = __bfloat16_as_ushort(l);
    split1(v.y, h, l); H.y = __bfloat16_as_ushort(h); L.y = __bfloat16_as_ushort(l);
    split1(v.z, h, l); H.z = __bfloat16_as_ushort(h); L.z = __bfloat16_as_ushort(l);
    split1(v.w, h, l); H.w = __bfloat16_as_ushort(h); L.w = __bfloat16_as_ushort(l);
    ((ushort4*)g_Whi)[i] = H;
    ((ushort4*)g_Wlo)[i] = L;
}

// pack [W_B ; W_C] (32 x 1024) and split. grid 32, blk 256 (float4 units)
__global__ void split_wbc_kernel(const float* __restrict__ WB,
                                 const float* __restrict__ WC) {
    int i = blockIdx.x * 256 + threadIdx.x;       // 0..8191 float4
    int row = (i * 4) >> 10;                      // 0..31
    const float4* src = (row < 16) ? (const float4*)WB : ((const float4*)WC - 4096);
    float4 v = src[i];
    ushort4 H, L;
    __nv_bfloat16 h, l;
    split1(v.x, h, l); H.x = __bfloat16_as_ushort(h); L.x = __bfloat16_as_ushort(l);
    split1(v.y, h, l); H.y = __bfloat16_as_ushort(h); L.y = __bfloat16_as_ushort(l);
    split1(v.z, h, l); H.z = __bfloat16_as_ushort(h); L.z = __bfloat16_as_ushort(l);
    split1(v.w, h, l); H.w = __bfloat16_as_ushort(h); L.w = __bfloat16_as_ushort(l);
    ((ushort4*)g_Wbch)[i] = H;
    ((ushort4*)g_Wbcl)[i] = L;
}

// ---------------------------------------------------------------------------
// Kernel 1: delta = softplus(X @ W^T + b), mma.sync bf16 3-term split.
// 128x128 CTA tile, BK=64, 2-stage cp.async, dynamic smem (4 x 18432 B).
// 48 iters = 3 passes x 16 chunks. SROW=72 elems (144B rows; 9r mod 8 perm).
// ---------------------------------------------------------------------------
#define SROW   72
#define SSTAGE (128 * SROW * 2)   // bytes per matrix per stage = 18432
#define GSMEM  (4 * SSTAGE)       // 73728

extern __shared__ __align__(16) char gsm[];

__global__ __launch_bounds__(256) void gemm_mma_kernel(const float* __restrict__ bias)
{
    const int tid  = threadIdx.x;
    const int wid  = tid >> 5;
    const int lane = tid & 31;
    const int wm   = wid >> 1;     // 0..3
    const int wn   = wid & 1;      // 0..1
    const int m0   = blockIdx.y * 128;
    const int n0   = blockIdx.x * 128;

    const uint32_t sAb = smem_u32(gsm);
    const uint32_t sBb = sAb + 2 * SSTAGE;

    float acc[2][8][4];
#pragma unroll
    for (int i = 0; i < 2; i++)
#pragma unroll
        for (int j = 0; j < 8; j++)
#pragma unroll
            for (int k = 0; k < 4; k++) acc[i][j][k] = 0.f;

    auto load_tile = [&](int it, int buf) {
        const int p  = it >> 4;
        const size_t kb = (size_t)(it & 15) * 128;   // bytes along K
        const char* Ab = (const char*)((p < 2)  ? g_Xhi : g_Xlo);
        const char* Bb = (const char*)((p == 1) ? g_Wlo : g_Whi);
#pragma unroll
        for (int i = 0; i < 4; i++) {
            const int unit = tid + i * 256;           // 0..1023
            const int row = unit >> 3, c = unit & 7;
            const char* srcA = Ab + (((size_t)(m0 + row)) << 11) + kb + c * 16;
            const char* srcB = Bb + (((size_t)(n0 + row)) << 11) + kb + c * 16;
            const uint32_t so = (uint32_t)buf * SSTAGE + row * 144 + c * 16;
            CP16(sAb + so, srcA);
            CP16(sBb + so, srcB);
        }
    };

    load_tile(0, 0); CP_COMMIT();
    load_tile(1, 1); CP_COMMIT();

    for (int it = 0; it < 48; it++) {
        CP_WAIT1();
        __syncthreads();
        const int buf = it & 1;
        const uint32_t ab = sAb + (uint32_t)buf * SSTAGE;
        const uint32_t bb = sBb + (uint32_t)buf * SSTAGE;

#pragma unroll
        for (int ks = 0; ks < 4; ks++) {
            uint32_t afr[2][4], bfr[4][4];
#pragma unroll
            for (int mi = 0; mi < 2; mi++) {
                const int row = wm * 32 + mi * 16 + (lane & 7) + ((lane >> 3) & 1) * 8;
                LDSM4(afr[mi], ab + row * 144 + ks * 32 + (lane >> 4) * 16);
            }
#pragma unroll
            for (int ni = 0; ni < 4; ni++) {
                const int row = wn * 64 + ni * 16 + (lane & 7) + ((lane >> 4) << 3);
                LDSM4(bfr[ni], bb + row * 144 + ks * 32 + ((lane >> 3) & 1) * 16);
            }
#pragma unroll
            for (int mi = 0; mi < 2; mi++)
#pragma unroll
                for (int nj = 0; nj < 8; nj++)
                    MMA16816(acc[mi][nj], afr[mi], bfr[nj >> 1][(nj & 1) * 2],
                             bfr[nj >> 1][(nj & 1) * 2 + 1]);
        }
        __syncthreads();
        if (it + 2 < 48) load_tile(it + 2, buf);
        CP_COMMIT();
    }

    const int tq = lane >> 2, tr = lane & 3;
#pragma unroll
    for (int mi = 0; mi < 2; mi++) {
        const int r0 = m0 + wm * 32 + mi * 16 + tq;
#pragma unroll
        for (int nj = 0; nj < 8; nj++) {
            const int c = n0 + wn * 64 + nj * 8 + tr * 2;
            const float bx = __ldg(bias + c), by = __ldg(bias + c + 1);
            float2 v0, v1;
            v0.x = softplus_f(acc[mi][nj][0] + bx);
            v0.y = softplus_f(acc[mi][nj][1] + by);
            v1.x = softplus_f(acc[mi][nj][2] + bx);
            v1.y = softplus_f(acc[mi][nj][3] + by);
            *(float2*)(g_delta + (size_t)r0 * DM + c)       = v0;
            *(float2*)(g_delta + (size_t)(r0 + 8) * DM + c) = v1;
        }
    }
}

// ---------------------------------------------------------------------------
// Kernel 2: B/C projections via mma.sync. M=64 tile, N=32, BK=32, 96 iters.
// grid = MTOT/64 = 64 CTAs, 128 threads. Writes g_B/g_C (b,l,n) directly.
// ---------------------------------------------------------------------------
#define BCROW 40

__global__ __launch_bounds__(128) void bc_mma_kernel(
    const float* __restrict__ bB, const float* __restrict__ bC)
{
    __shared__ __nv_bfloat16 sA[2][64 * BCROW];
    __shared__ __nv_bfloat16 sB[2][32 * BCROW];

    const int tid  = threadIdx.x;
    const int wid  = tid >> 5;     // 0..3
    const int lane = tid & 31;
    const int m0   = blockIdx.x * 64;

    const uint32_t sAb = smem_u32(sA);
    const uint32_t sBb = smem_u32(sB);

    float acc[4][4];
#pragma unroll
    for (int j = 0; j < 4; j++)
#pragma unroll
        for (int k = 0; k < 4; k++) acc[j][k] = 0.f;

    auto load_tile = [&](int it, int buf) {
        const int p  = it >> 5;
        const size_t kb = (size_t)(it & 31) * 64;
        const char* Ab = (const char*)((p < 2)  ? g_Xhi : g_Xlo);
        const char* Bb = (const char*)((p == 1) ? g_Wbcl : g_Wbch);
#pragma unroll
        for (int i = 0; i < 2; i++) {   // A: 64 rows x 4 c
            const int unit = tid + i * 128;
            const int row = unit >> 2, c = unit & 3;
            CP16(sAb + (uint32_t)buf * (64 * BCROW * 2) + row * 80 + c * 16,
                 Ab + (((size_t)(m0 + row)) << 11) + kb + c * 16);
        }
        {   // B: 32 rows x 4 c
            const int row = tid >> 2, c = tid & 3;
            CP16(sBb + (uint32_t)buf * (32 * BCROW * 2) + row * 80 + c * 16,
                 Bb + (((size_t)row) << 11) + kb + c * 16);
        }
    };

    load_tile(0, 0); CP_COMMIT();
    load_tile(1, 1); CP_COMMIT();

    for (int it = 0; it < 96; it++) {
        CP_WAIT1();
        __syncthreads();
        const int buf = it & 1;
        const uint32_t ab = sAb + (uint32_t)buf * (64 * BCROW * 2);
        const uint32_t bb = sBb + (uint32_t)buf * (32 * BCROW * 2);

#pragma unroll
        for (int ks = 0; ks < 2; ks++) {
            uint32_t afr[4], bfr[2][4];
            {
                const int row = wid * 16 + (lane & 7) + ((lane >> 3) & 1) * 8;
                LDSM4(afr, ab + row * 80 + ks * 32 + (lane >> 4) * 16);
            }
#pragma unroll
            for (int ni = 0; ni < 2; ni++) {
                const int row = ni * 16 + (lane & 7) + ((lane >> 4) << 3);
                LDSM4(bfr[ni], bb + row * 80 + ks * 32 + ((lane >> 3) & 1) * 16);
            }
#pragma unroll
            for (int nj = 0; nj < 4; nj++)
                MMA16816(acc[nj], afr, bfr[nj >> 1][(nj & 1) * 2],
                         bfr[nj >> 1][(nj & 1) * 2 + 1]);
        }
        __syncthreads();
        if (it + 2 < 96) load_tile(it + 2, buf);
        CP_COMMIT();
    }

    const int tq = lane >> 2, tr = lane & 3;
    const int r0 = m0 + wid * 16 + tq;
#pragma unroll
    for (int nj = 0; nj < 4; nj++) {
        const int c = nj * 8 + tr * 2;     // 0..30, even
        const bool isB = (c < 16);
        const int cc = isB ? c : c - 16;
        const float bx = isB ? __ldg(bB + cc) : __ldg(bC + cc);
        const float by = isB ? __ldg(bB + cc + 1) : __ldg(bC + cc + 1);
        float* base = isB ? g_B : g_C;
        float2 v0, v1;
        v0.x = acc[nj][0] + bx; v0.y = acc[nj][1] + by;
        v1.x = acc[nj][2] + bx; v1.y = acc[nj][3] + by;
        *(float2*)(base + (size_t)r0 * DS + cc)       = v0;
        *(float2*)(base + (size_t)(r0 + 8) * DS + cc) = v1;
    }
}

// ---------------------------------------------------------------------------
// Kernel 3: transpose delta (b,l,d) -> (b,d,l)
// ---------------------------------------------------------------------------
__global__ void transpose_delta_kernel()
{
    __shared__ float t0[32][33];
    const int b  = blockIdx.z;
    const int d0 = blockIdx.x * 32;
    const int l0 = blockIdx.y * 32;
    const int tx = threadIdx.x, ty = threadIdx.y;

#pragma unroll
    for (int i = 0; i < 32; i += 8)
        t0[ty + i][tx] = g_delta[((size_t)(b * SEQ + l0 + ty + i)) * DM + d0 + tx];
    __syncthreads();
#pragma unroll
    for (int i = 0; i < 32; i += 8)
        g_deltaT[((size_t)(b * DM + d0 + ty + i)) * SEQ + l0 + tx] = t0[tx][ty + i];
}

// ---------------------------------------------------------------------------
// Scan pass 1: per chunk, P = prod(dA), q = h(end | h0=0).
// ---------------------------------------------------------------------------
__global__ __launch_bounds__(128) void scan_pass1(const float* __restrict__ logA)
{
    __shared__ __align__(16) float sB[CS * DS];

    const int b  = blockIdx.z;
    const int c  = blockIdx.y;
    const int d0 = blockIdx.x * 8;
    const int g  = threadIdx.x >> 4;
    const int n  = threadIdx.x & 15;
    const int d  = d0 + g;
    const int bd = b * DM + d;

    {
        const float4* src = (const float4*)(g_B + ((size_t)b * SEQ + c * CS) * DS);
        float4* dst = (float4*)sB;
        for (int i = threadIdx.x; i < CS * DS / 4; i += 128) dst[i] = src[i];
    }
    __syncthreads();

    const float A = -expf(logA[d * DS + n]);
    const float4* dp = (const float4*)(g_deltaT + (size_t)bd * SEQ + c * CS);
    const float4* xp = (const float4*)(g_xT     + (size_t)bd * SEQ + c * CS);

    float h = 0.f, P = 1.f;
    for (int q4 = 0; q4 < CS / 4; q4++) {
        float4 dv = dp[q4], xv = xp[q4];
        const int l = q4 * 4;
        float b0 = sB[(l + 0) * DS + n], b1 = sB[(l + 1) * DS + n];
        float b2 = sB[(l + 2) * DS + n], b3 = sB[(l + 3) * DS + n];
        float dA;
        dA = __expf(dv.x * A); P *= dA; h = fmaf(dA, h, dv.x * xv.x * b0);
        dA = __expf(dv.y * A); P *= dA; h = fmaf(dA, h, dv.y * xv.y * b1);
        dA = __expf(dv.z * A); P *= dA; h = fmaf(dA, h, dv.z * xv.z * b2);
        dA = __expf(dv.w * A); P *= dA; h = fmaf(dA, h, dv.w * xv.w * b3);
    }
    const size_t idx = ((size_t)bd * CH + c) * DS + n;
    g_P[idx] = P;
    g_q[idx] = h;
}

// ---------------------------------------------------------------------------
// Scan pass 2: combine chunk summaries -> h0 per chunk.
// ---------------------------------------------------------------------------
__global__ void scan_combine()
{
    const int t = blockIdx.x * 256 + threadIdx.x;
    const int bd = t >> 4;
    const int n  = t & 15;
    float h = 0.f;
    for (int c = 0; c < CH; c++) {
        const size_t idx = ((size_t)bd * CH + c) * DS + n;
        g_h0[idx] = h;
        h = fmaf(g_P[idx], h, g_q[idx]);
    }
}

// ---------------------------------------------------------------------------
// Scan pass 3: rescan from h0, emit y.
// ---------------------------------------------------------------------------
__global__ __launch_bounds__(128) void scan_pass3(const float* __restrict__ logA)
{
    __shared__ __align__(16) float sB[CS * DS];
    __shared__ __align__(16) float sC[CS * DS];

    const int b  = blockIdx.z;
    const int c  = blockIdx.y;
    const int d0 = blockIdx.x * 8;
    const int g  = threadIdx.x >> 4;
    const int n  = threadIdx.x & 15;
    const int d  = d0 + g;
    const int bd = b * DM + d;

    {
        const float4* srcB = (const float4*)(g_B + ((size_t)b * SEQ + c * CS) * DS);
        const float4* srcC = (const float4*)(g_C + ((size_t)b * SEQ + c * CS) * DS);
        float4* dstB = (float4*)sB;
        float4* dstC = (float4*)sC;
        for (int i = threadIdx.x; i < CS * DS / 4; i += 128) {
            dstB[i] = srcB[i];
            dstC[i] = srcC[i];
        }
    }
    __syncthreads();

    const float A = -expf(logA[d * DS + n]);
    const float4* dp = (const float4*)(g_deltaT + (size_t)bd * SEQ + c * CS);
    const float4* xp = (const float4*)(g_xT     + (size_t)bd * SEQ + c * CS);
    float4*       yp = (float4*)(g_yT           + (size_t)bd * SEQ + c * CS);

    float h = g_h0[((size_t)bd * CH + c) * DS + n];

#define SSM_STEP(DV, XV, BV, CV, YO)                                   \
    {                                                                  \
        float dA = __expf((DV) * A);                                   \
        h = fmaf(dA, h, (DV) * (XV) * (BV));                           \
        float p = h * (CV);                                            \
        p += __shfl_xor_sync(0xffffffffu, p, 8);                       \
        p += __shfl_xor_sync(0xffffffffu, p, 4);                       \
        p += __shfl_xor_sync(0xffffffffu, p, 2);                       \
        p += __shfl_xor_sync(0xffffffffu, p, 1);                       \
        (YO) = p;                                                      \
    }

    for (int q4 = 0; q4 < CS / 4; q4++) {
        float4 dv = dp[q4], xv = xp[q4];
        const int l = q4 * 4;
        float b0 = sB[(l + 0) * DS + n], b1 = sB[(l + 1) * DS + n];
        float b2 = sB[(l + 2) * DS + n], b3 = sB[(l + 3) * DS + n];
        float c0 = sC[(l + 0) * DS + n], c1 = sC[(l + 1) * DS + n];
        float c2 = sC[(l + 2) * DS + n], c3 = sC[(l + 3) * DS + n];
        float4 y;
        SSM_STEP(dv.x, xv.x, b0, c0, y.x);
        SSM_STEP(dv.y, xv.y, b1, c1, y.y);
        SSM_STEP(dv.z, xv.z, b2, c2, y.z);
        SSM_STEP(dv.w, xv.w, b3, c3, y.w);
        if (n == 0) yp[q4] = y;
    }
#undef SSM_STEP
}

// ---------------------------------------------------------------------------
// Kernel 5: out[b,l,d] = yT[b,d,l] + x[b,l,d] * D_skip[d]
// ---------------------------------------------------------------------------
__global__ void out_kernel(const float* __restrict__ X,
                           const float* __restrict__ Dskip,
                           float* __restrict__ out)
{
    __shared__ float t[32][33];
    const int b  = blockIdx.z;
    const int l0 = blockIdx.x * 32;
    const int d0 = blockIdx.y * 32;
    const int tx = threadIdx.x, ty = threadIdx.y;

#pragma unroll
    for (int i = 0; i < 32; i += 8)
        t[ty + i][tx] = g_yT[((size_t)(b * DM + d0 + ty + i)) * SEQ + l0 + tx];
    __syncthreads();
    const float dsk = Dskip[d0 + tx];
#pragma unroll
    for (int i = 0; i < 32; i += 8) {
        size_t idx = ((size_t)(b * SEQ + l0 + ty + i)) * DM + d0 + tx;
        out[idx] = t[tx][ty + i] + X[idx] * dsk;
    }
}

// ---------------------------------------------------------------------------
extern "C" void kernel_launch(void* const* d_in, const int* in_sizes, int n_in,
                              void* d_out, int out_size)
{
    (void)in_sizes; (void)n_in; (void)out_size;
    const float* x    = (const float*)d_in[0];
    const float* W_B  = (const float*)d_in[1];
    const float* b_B  = (const float*)d_in[2];
    const float* W_C  = (const float*)d_in[3];
    const float* b_C  = (const float*)d_in[4];
    const float* W_dt = (const float*)d_in[5];
    const float* b_dt = (const float*)d_in[6];
    const float* logA = (const float*)d_in[7];
    const float* Dsk  = (const float*)d_in[8];
    float* out = (float*)d_out;

    static bool attr_set = false;
    if (!attr_set) {
        cudaFuncSetAttribute(gemm_mma_kernel,
                             cudaFuncAttributeMaxDynamicSharedMemorySize, GSMEM);
        attr_set = true;
    }

    split_x_t_kernel<<<dim3(DM / 32, SEQ / 32, BATCH), dim3(32, 8)>>>(x);
    split_w_kernel<<<(DM * DM / 4) / 256, 256>>>(W_dt);
    split_wbc_kernel<<<32, 256>>>(W_B, W_C);
    gemm_mma_kernel<<<dim3(DM / 128, MTOT / 128), 256, GSMEM>>>(b_dt);
    bc_mma_kernel<<<MTOT / 64, 128>>>(b_B, b_C);
    transpose_delta_kernel<<<dim3(DM / 32, SEQ / 32, BATCH), dim3(32, 8)>>>();
    scan_pass1<<<dim3(DM / 8, CH, BATCH), 128>>>(logA);
    scan_combine<<<(BATCH * DM * DS) / 256, 256>>>();
    scan_pass3<<<dim3(DM / 8, CH, BATCH), 128>>>(logA);
    out_kernel<<<dim3(SEQ / 32, DM / 32, BATCH), dim3(32, 8)>>>(x, Dsk, out);
}

// round 6
// speedup vs baseline: 1.1767x; 1.1767x over previous
#include <cuda_runtime.h>
#include <cuda_bf16.h>
#include <cstdint>

#define BATCH 2
#define SEQ   2048
#define DM    1024
#define DS    16
#define MTOT  (BATCH*SEQ)   // 4096
#define CH    16            // scan chunks
#define CS    (SEQ/CH)      // 128 steps per chunk

// ----------------------------- scratch globals -----------------------------
__device__ float g_delta [MTOT*DM];       // (b,l,d)
__device__ float g_deltaT[BATCH*DM*SEQ];  // (b,d,l)
__device__ float g_xT    [BATCH*DM*SEQ];  // (b,d,l)
__device__ float g_B     [MTOT*DS];       // (b,l,n)
__device__ float g_C     [MTOT*DS];       // (b,l,n)
__device__ float g_yT    [BATCH*DM*SEQ];  // (b,d,l)
__device__ float g_P     [BATCH*DM*CH*DS];
__device__ float g_q     [BATCH*DM*CH*DS];
__device__ float g_h0    [BATCH*DM*CH*DS];
__device__ __nv_bfloat16 g_Xhi[MTOT*DM];
__device__ __nv_bfloat16 g_Xlo[MTOT*DM];
__device__ __nv_bfloat16 g_Whi[DM*DM];
__device__ __nv_bfloat16 g_Wlo[DM*DM];
__device__ __nv_bfloat16 g_Wbch[32*DM];   // [W_B ; W_C] hi
__device__ __nv_bfloat16 g_Wbcl[32*DM];   // [W_B ; W_C] lo

__device__ __forceinline__ float softplus_f(float z) {
    return fmaxf(z, 0.f) + log1pf(expf(-fabsf(z)));
}

__device__ __forceinline__ uint32_t smem_u32(const void* p) {
    uint32_t a;
    asm("{ .reg .u64 t; cvta.to.shared.u64 t, %1; cvt.u32.u64 %0, t; }"
        : "=r"(a) : "l"(p));
    return a;
}

#define CP16(dst, src) \
    asm volatile("cp.async.cg.shared.global [%0], [%1], 16;" :: "r"(dst), "l"(src))
#define CP_COMMIT() asm volatile("cp.async.commit_group;" ::: "memory")
#define CP_WAIT1()  asm volatile("cp.async.wait_group 1;" ::: "memory")

#define LDSM4(r, addr) \
    asm volatile("ldmatrix.sync.aligned.m8n8.x4.shared.b16 {%0,%1,%2,%3}, [%4];" \
        : "=r"((r)[0]), "=r"((r)[1]), "=r"((r)[2]), "=r"((r)[3]) : "r"(addr))

#define MMA16816(d, a, b0, b1) \
    asm volatile("mma.sync.aligned.m16n8k16.row.col.f32.bf16.bf16.f32 " \
        "{%0,%1,%2,%3}, {%4,%5,%6,%7}, {%8,%9}, {%0,%1,%2,%3};" \
        : "+f"((d)[0]), "+f"((d)[1]), "+f"((d)[2]), "+f"((d)[3]) \
        : "r"((a)[0]), "r"((a)[1]), "r"((a)[2]), "r"((a)[3]), "r"(b0), "r"(b1))

// ---------------------------------------------------------------------------
// Prep kernels
// ---------------------------------------------------------------------------
__device__ __forceinline__ void split1(float v, __nv_bfloat16& H, __nv_bfloat16& L) {
    H = __float2bfloat16_rn(v);
    L = __float2bfloat16_rn(v - __bfloat162float(H));
}

// split x AND transpose x -> g_xT in one pass. grid (DM/32, SEQ/32, BATCH), blk (32,8)
__global__ void split_x_t_kernel(const float* __restrict__ x) {
    __shared__ float t[32][33];
    const int b  = blockIdx.z;
    const int d0 = blockIdx.x * 32;
    const int l0 = blockIdx.y * 32;
    const int tx = threadIdx.x, ty = threadIdx.y;
#pragma unroll
    for (int i = 0; i < 32; i += 8) {
        const size_t src = ((size_t)(b * SEQ + l0 + ty + i)) * DM + d0 + tx;
        float v = x[src];
        t[ty + i][tx] = v;
        __nv_bfloat16 H, L; split1(v, H, L);
        g_Xhi[src] = H;
        g_Xlo[src] = L;
    }
    __syncthreads();
#pragma unroll
    for (int i = 0; i < 32; i += 8)
        g_xT[((size_t)(b * DM + d0 + ty + i)) * SEQ + l0 + tx] = t[tx][ty + i];
}

__global__ void split_w_kernel(const float* __restrict__ src) {
    int i = blockIdx.x * 256 + threadIdx.x;
    float4 v = ((const float4*)src)[i];
    ushort4 H, L;
    __nv_bfloat16 h, l;
    split1(v.x, h, l); H.x = __bfloat16_as_ushort(h); L.x = __bfloat16_as_ushort(l);
    split1(v.y, h, l); H.y = __bfloat16_as_ushort(h); L.y = __bfloat16_as_ushort(l);
    split1(v.z, h, l); H.z = __bfloat16_as_ushort(h); L.z = __bfloat16_as_ushort(l);
    split1(v.w, h, l); H.w = __bfloat16_as_ushort(h); L.w = __bfloat16_as_ushort(l);
    ((ushort4*)g_Whi)[i] = H;
    ((ushort4*)g_Wlo)[i] = L;
}

// pack [W_B ; W_C] (32 x 1024) and split. grid 32, blk 256 (float4 units)
__global__ void split_wbc_kernel(const float* __restrict__ WB,
                                 const float* __restrict__ WC) {
    int i = blockIdx.x * 256 + threadIdx.x;       // 0..8191 float4
    int row = (i * 4) >> 10;                      // 0..31
    const float4* src = (row < 16) ? (const float4*)WB : ((const float4*)WC - 4096);
    float4 v = src[i];
    ushort4 H, L;
    __nv_bfloat16 h, l;
    split1(v.x, h, l); H.x = __bfloat16_as_ushort(h); L.x = __bfloat16_as_ushort(l);
    split1(v.y, h, l); H.y = __bfloat16_as_ushort(h); L.y = __bfloat16_as_ushort(l);
    split1(v.z, h, l); H.z = __bfloat16_as_ushort(h); L.z = __bfloat16_as_ushort(l);
    split1(v.w, h, l); H.w = __bfloat16_as_ushort(h); L.w = __bfloat16_as_ushort(l);
    ((ushort4*)g_Wbch)[i] = H;
    ((ushort4*)g_Wbcl)[i] = L;
}

// ---------------------------------------------------------------------------
// Kernel 1: delta = softplus(X @ W^T + b), mma.sync bf16 3-term split.
// 128x128 CTA tile, BK=64, 2-stage cp.async, dynamic smem (4 x 18432 B).
// __launch_bounds__(256, 2): cap regs at 128 so 2 CTAs/SM co-reside ->
// 296 CTA slots >= 256 grid CTAs (single wave, 16 warps/SM).
// ---------------------------------------------------------------------------
#define SROW   72
#define SSTAGE (128 * SROW * 2)   // bytes per matrix per stage = 18432
#define GSMEM  (4 * SSTAGE)       // 73728

extern __shared__ __align__(16) char gsm[];

__global__ __launch_bounds__(256, 2) void gemm_mma_kernel(const float* __restrict__ bias)
{
    const int tid  = threadIdx.x;
    const int wid  = tid >> 5;
    const int lane = tid & 31;
    const int wm   = wid >> 1;     // 0..3
    const int wn   = wid & 1;      // 0..1
    const int m0   = blockIdx.y * 128;
    const int n0   = blockIdx.x * 128;

    const uint32_t sAb = smem_u32(gsm);
    const uint32_t sBb = sAb + 2 * SSTAGE;

    float acc[2][8][4];
#pragma unroll
    for (int i = 0; i < 2; i++)
#pragma unroll
        for (int j = 0; j < 8; j++)
#pragma unroll
            for (int k = 0; k < 4; k++) acc[i][j][k] = 0.f;

    auto load_tile = [&](int it, int buf) {
        const int p  = it >> 4;
        const size_t kb = (size_t)(it & 15) * 128;   // bytes along K
        const char* Ab = (const char*)((p < 2)  ? g_Xhi : g_Xlo);
        const char* Bb = (const char*)((p == 1) ? g_Wlo : g_Whi);
#pragma unroll
        for (int i = 0; i < 4; i++) {
            const int unit = tid + i * 256;           // 0..1023
            const int row = unit >> 3, c = unit & 7;
            const char* srcA = Ab + (((size_t)(m0 + row)) << 11) + kb + c * 16;
            const char* srcB = Bb + (((size_t)(n0 + row)) << 11) + kb + c * 16;
            const uint32_t so = (uint32_t)buf * SSTAGE + row * 144 + c * 16;
            CP16(sAb + so, srcA);
            CP16(sBb + so, srcB);
        }
    };

    load_tile(0, 0); CP_COMMIT();
    load_tile(1, 1); CP_COMMIT();

    for (int it = 0; it < 48; it++) {
        CP_WAIT1();
        __syncthreads();
        const int buf = it & 1;
        const uint32_t ab = sAb + (uint32_t)buf * SSTAGE;
        const uint32_t bb = sBb + (uint32_t)buf * SSTAGE;

#pragma unroll
        for (int ks = 0; ks < 4; ks++) {
            uint32_t afr[2][4], bfr[4][4];
#pragma unroll
            for (int mi = 0; mi < 2; mi++) {
                const int row = wm * 32 + mi * 16 + (lane & 7) + ((lane >> 3) & 1) * 8;
                LDSM4(afr[mi], ab + row * 144 + ks * 32 + (lane >> 4) * 16);
            }
#pragma unroll
            for (int ni = 0; ni < 4; ni++) {
                const int row = wn * 64 + ni * 16 + (lane & 7) + ((lane >> 4) << 3);
                LDSM4(bfr[ni], bb + row * 144 + ks * 32 + ((lane >> 3) & 1) * 16);
            }
#pragma unroll
            for (int mi = 0; mi < 2; mi++)
#pragma unroll
                for (int nj = 0; nj < 8; nj++)
                    MMA16816(acc[mi][nj], afr[mi], bfr[nj >> 1][(nj & 1) * 2],
                             bfr[nj >> 1][(nj & 1) * 2 + 1]);
        }
        __syncthreads();
        if (it + 2 < 48) load_tile(it + 2, buf);
        CP_COMMIT();
    }

    const int tq = lane >> 2, tr = lane & 3;
#pragma unroll
    for (int mi = 0; mi < 2; mi++) {
        const int r0 = m0 + wm * 32 + mi * 16 + tq;
#pragma unroll
        for (int nj = 0; nj < 8; nj++) {
            const int c = n0 + wn * 64 + nj * 8 + tr * 2;
            const float bx = __ldg(bias + c), by = __ldg(bias + c + 1);
            float2 v0, v1;
            v0.x = softplus_f(acc[mi][nj][0] + bx);
            v0.y = softplus_f(acc[mi][nj][1] + by);
            v1.x = softplus_f(acc[mi][nj][2] + bx);
            v1.y = softplus_f(acc[mi][nj][3] + by);
            *(float2*)(g_delta + (size_t)r0 * DM + c)       = v0;
            *(float2*)(g_delta + (size_t)(r0 + 8) * DM + c) = v1;
        }
    }
}

// ---------------------------------------------------------------------------
// Kernel 2: B/C projections via mma.sync. M=64 tile, N=32, BK=32, 96 iters.
// ---------------------------------------------------------------------------
#define BCROW 40

__global__ __launch_bounds__(128) void bc_mma_kernel(
    const float* __restrict__ bB, const float* __restrict__ bC)
{
    __shared__ __nv_bfloat16 sA[2][64 * BCROW];
    __shared__ __nv_bfloat16 sB[2][32 * BCROW];

    const int tid  = threadIdx.x;
    const int wid  = tid >> 5;     // 0..3
    const int lane = tid & 31;
    const int m0   = blockIdx.x * 64;

    const uint32_t sAb = smem_u32(sA);
    const uint32_t sBb = smem_u32(sB);

    float acc[4][4];
#pragma unroll
    for (int j = 0; j < 4; j++)
#pragma unroll
        for (int k = 0; k < 4; k++) acc[j][k] = 0.f;

    auto load_tile = [&](int it, int buf) {
        const int p  = it >> 5;
        const size_t kb = (size_t)(it & 31) * 64;
        const char* Ab = (const char*)((p < 2)  ? g_Xhi : g_Xlo);
        const char* Bb = (const char*)((p == 1) ? g_Wbcl : g_Wbch);
#pragma unroll
        for (int i = 0; i < 2; i++) {
            const int unit = tid + i * 128;
            const int row = unit >> 2, c = unit & 3;
            CP16(sAb + (uint32_t)buf * (64 * BCROW * 2) + row * 80 + c * 16,
                 Ab + (((size_t)(m0 + row)) << 11) + kb + c * 16);
        }
        {
            const int row = tid >> 2, c = tid & 3;
            CP16(sBb + (uint32_t)buf * (32 * BCROW * 2) + row * 80 + c * 16,
                 Bb + (((size_t)row) << 11) + kb + c * 16);
        }
    };

    load_tile(0, 0); CP_COMMIT();
    load_tile(1, 1); CP_COMMIT();

    for (int it = 0; it < 96; it++) {
        CP_WAIT1();
        __syncthreads();
        const int buf = it & 1;
        const uint32_t ab = sAb + (uint32_t)buf * (64 * BCROW * 2);
        const uint32_t bb = sBb + (uint32_t)buf * (32 * BCROW * 2);

#pragma unroll
        for (int ks = 0; ks < 2; ks++) {
            uint32_t afr[4], bfr[2][4];
            {
                const int row = wid * 16 + (lane & 7) + ((lane >> 3) & 1) * 8;
                LDSM4(afr, ab + row * 80 + ks * 32 + (lane >> 4) * 16);
            }
#pragma unroll
            for (int ni = 0; ni < 2; ni++) {
                const int row = ni * 16 + (lane & 7) + ((lane >> 4) << 3);
                LDSM4(bfr[ni], bb + row * 80 + ks * 32 + ((lane >> 3) & 1) * 16);
            }
#pragma unroll
            for (int nj = 0; nj < 4; nj++)
                MMA16816(acc[nj], afr, bfr[nj >> 1][(nj & 1) * 2],
                         bfr[nj >> 1][(nj & 1) * 2 + 1]);
        }
        __syncthreads();
        if (it + 2 < 96) load_tile(it + 2, buf);
        CP_COMMIT();
    }

    const int tq = lane >> 2, tr = lane & 3;
    const int r0 = m0 + wid * 16 + tq;
#pragma unroll
    for (int nj = 0; nj < 4; nj++) {
        const int c = nj * 8 + tr * 2;
        const bool isB = (c < 16);
        const int cc = isB ? c : c - 16;
        const float bx = isB ? __ldg(bB + cc) : __ldg(bC + cc);
        const float by = isB ? __ldg(bB + cc + 1) : __ldg(bC + cc + 1);
        float* base = isB ? g_B : g_C;
        float2 v0, v1;
        v0.x = acc[nj][0] + bx; v0.y = acc[nj][1] + by;
        v1.x = acc[nj][2] + bx; v1.y = acc[nj][3] + by;
        *(float2*)(base + (size_t)r0 * DS + cc)       = v0;
        *(float2*)(base + (size_t)(r0 + 8) * DS + cc) = v1;
    }
}

// ---------------------------------------------------------------------------
// Kernel 3: transpose delta (b,l,d) -> (b,d,l)
// ---------------------------------------------------------------------------
__global__ void transpose_delta_kernel()
{
    __shared__ float t0[32][33];
    const int b  = blockIdx.z;
    const int d0 = blockIdx.x * 32;
    const int l0 = blockIdx.y * 32;
    const int tx = threadIdx.x, ty = threadIdx.y;

#pragma unroll
    for (int i = 0; i < 32; i += 8)
        t0[ty + i][tx] = g_delta[((size_t)(b * SEQ + l0 + ty + i)) * DM + d0 + tx];
    __syncthreads();
#pragma unroll
    for (int i = 0; i < 32; i += 8)
        g_deltaT[((size_t)(b * DM + d0 + ty + i)) * SEQ + l0 + tx] = t0[tx][ty + i];
}

// ---------------------------------------------------------------------------
// Scan pass 1: 8-lane groups, 2 states (n, n+8) per lane.
// Grid (DM/16, CH, BATCH), block 128 = 16 d-groups.
// ---------------------------------------------------------------------------
__global__ __launch_bounds__(128) void scan_pass1(const float* __restrict__ logA)
{
    __shared__ __align__(16) float sB[CS * DS];

    const int b  = blockIdx.z;
    const int c  = blockIdx.y;
    const int d0 = blockIdx.x * 16;
    const int g  = threadIdx.x >> 3;
    const int n  = threadIdx.x & 7;
    const int d  = d0 + g;
    const int bd = b * DM + d;

    {
        const float4* src = (const float4*)(g_B + ((size_t)b * SEQ + c * CS) * DS);
        float4* dst = (float4*)sB;
        for (int i = threadIdx.x; i < CS * DS / 4; i += 128) dst[i] = src[i];
    }
    __syncthreads();

    const float A0 = -expf(logA[d * DS + n]);
    const float A1 = -expf(logA[d * DS + n + 8]);
    const float4* dp = (const float4*)(g_deltaT + (size_t)bd * SEQ + c * CS);
    const float4* xp = (const float4*)(g_xT     + (size_t)bd * SEQ + c * CS);

    float h0 = 0.f, h1 = 0.f, P0 = 1.f, P1 = 1.f;
#define P1_STEP(DV, XV, L)                                              \
    {                                                                   \
        const float bb0 = sB[(L) * DS + n], bb1 = sB[(L) * DS + n + 8]; \
        const float dx = (DV) * (XV);                                   \
        float dA0 = __expf((DV) * A0), dA1 = __expf((DV) * A1);         \
        P0 *= dA0; P1 *= dA1;                                           \
        h0 = fmaf(dA0, h0, dx * bb0);                                   \
        h1 = fmaf(dA1, h1, dx * bb1);                                   \
    }
    for (int q4 = 0; q4 < CS / 4; q4++) {
        float4 dv = dp[q4], xv = xp[q4];
        const int l = q4 * 4;
        P1_STEP(dv.x, xv.x, l + 0);
        P1_STEP(dv.y, xv.y, l + 1);
        P1_STEP(dv.z, xv.z, l + 2);
        P1_STEP(dv.w, xv.w, l + 3);
    }
#undef P1_STEP
    const size_t idx = ((size_t)bd * CH + c) * DS + n;
    g_P[idx] = P0;     g_q[idx] = h0;
    g_P[idx + 8] = P1; g_q[idx + 8] = h1;
}

// ---------------------------------------------------------------------------
// Scan pass 2: combine chunk summaries -> h0 per chunk.
// ---------------------------------------------------------------------------
__global__ void scan_combine()
{
    const int t = blockIdx.x * 256 + threadIdx.x;
    const int bd = t >> 4;
    const int n  = t & 15;
    float h = 0.f;
    for (int c = 0; c < CH; c++) {
        const size_t idx = ((size_t)bd * CH + c) * DS + n;
        g_h0[idx] = h;
        h = fmaf(g_P[idx], h, g_q[idx]);
    }
}

// ---------------------------------------------------------------------------
// Scan pass 3: rescan from h0, emit y. 8-lane groups, 2 states per lane,
// 3-level butterfly + local pair add.
// ---------------------------------------------------------------------------
__global__ __launch_bounds__(128) void scan_pass3(const float* __restrict__ logA)
{
    __shared__ __align__(16) float sB[CS * DS];
    __shared__ __align__(16) float sC[CS * DS];

    const int b  = blockIdx.z;
    const int c  = blockIdx.y;
    const int d0 = blockIdx.x * 16;
    const int g  = threadIdx.x >> 3;
    const int n  = threadIdx.x & 7;
    const int d  = d0 + g;
    const int bd = b * DM + d;

    {
        const float4* srcB = (const float4*)(g_B + ((size_t)b * SEQ + c * CS) * DS);
        const float4* srcC = (const float4*)(g_C + ((size_t)b * SEQ + c * CS) * DS);
        float4* dstB = (float4*)sB;
        float4* dstC = (float4*)sC;
        for (int i = threadIdx.x; i < CS * DS / 4; i += 128) {
            dstB[i] = srcB[i];
            dstC[i] = srcC[i];
        }
    }
    __syncthreads();

    const float A0 = -expf(logA[d * DS + n]);
    const float A1 = -expf(logA[d * DS + n + 8]);
    const float4* dp = (const float4*)(g_deltaT + (size_t)bd * SEQ + c * CS);
    const float4* xp = (const float4*)(g_xT     + (size_t)bd * SEQ + c * CS);
    float4*       yp = (float4*)(g_yT           + (size_t)bd * SEQ + c * CS);

    const size_t hidx = ((size_t)bd * CH + c) * DS + n;
    float h0 = g_h0[hidx];
    float h1 = g_h0[hidx + 8];

#define SSM_STEP(DV, XV, L, YO)                                          \
    {                                                                    \
        const float bb0 = sB[(L) * DS + n], bb1 = sB[(L) * DS + n + 8];  \
        const float cc0 = sC[(L) * DS + n], cc1 = sC[(L) * DS + n + 8];  \
        const float dx = (DV) * (XV);                                    \
        float dA0 = __expf((DV) * A0), dA1 = __expf((DV) * A1);          \
        h0 = fmaf(dA0, h0, dx * bb0);                                    \
        h1 = fmaf(dA1, h1, dx * bb1);                                    \
        float p = fmaf(h1, cc1, h0 * cc0);                               \
        p += __shfl_xor_sync(0xffffffffu, p, 4);                         \
        p += __shfl_xor_sync(0xffffffffu, p, 2);                         \
        p += __shfl_xor_sync(0xffffffffu, p, 1);                         \
        (YO) = p;                                                        \
    }

    for (int q4 = 0; q4 < CS / 4; q4++) {
        float4 dv = dp[q4], xv = xp[q4];
        const int l = q4 * 4;
        float4 y;
        SSM_STEP(dv.x, xv.x, l + 0, y.x);
        SSM_STEP(dv.y, xv.y, l + 1, y.y);
        SSM_STEP(dv.z, xv.z, l + 2, y.z);
        SSM_STEP(dv.w, xv.w, l + 3, y.w);
        if (n == 0) yp[q4] = y;
    }
#undef SSM_STEP
}

// ---------------------------------------------------------------------------
// Kernel 5: out[b,l,d] = yT[b,d,l] + x[b,l,d] * D_skip[d]
// ---------------------------------------------------------------------------
__global__ void out_kernel(const float* __restrict__ X,
                           const float* __restrict__ Dskip,
                           float* __restrict__ out)
{
    __shared__ float t[32][33];
    const int b  = blockIdx.z;
    const int l0 = blockIdx.x * 32;
    const int d0 = blockIdx.y * 32;
    const int tx = threadIdx.x, ty = threadIdx.y;

#pragma unroll
    for (int i = 0; i < 32; i += 8)
        t[ty + i][tx] = g_yT[((size_t)(b * DM + d0 + ty + i)) * SEQ + l0 + tx];
    __syncthreads();
    const float dsk = Dskip[d0 + tx];
#pragma unroll
    for (int i = 0; i < 32; i += 8) {
        size_t idx = ((size_t)(b * SEQ + l0 + ty + i)) * DM + d0 + tx;
        out[idx] = t[tx][ty + i] + X[idx] * dsk;
    }
}

// ---------------------------------------------------------------------------
extern "C" void kernel_launch(void* const* d_in, const int* in_sizes, int n_in,
                              void* d_out, int out_size)
{
    (void)in_sizes; (void)n_in; (void)out_size;
    const float* x    = (const float*)d_in[0];
    const float* W_B  = (const float*)d_in[1];
    const float* b_B  = (const float*)d_in[2];
    const float* W_C  = (const float*)d_in[3];
    const float* b_C  = (const float*)d_in[4];
    const float* W_dt = (const float*)d_in[5];
    const float* b_dt = (const float*)d_in[6];
    const float* logA = (const float*)d_in[7];
    const float* Dsk  = (const float*)d_in[8];
    float* out = (float*)d_out;

    static bool attr_set = false;
    if (!attr_set) {
        cudaFuncSetAttribute(gemm_mma_kernel,
                             cudaFuncAttributeMaxDynamicSharedMemorySize, GSMEM);
        attr_set = true;
    }

    split_x_t_kernel<<<dim3(DM / 32, SEQ / 32, BATCH), dim3(32, 8)>>>(x);
    split_w_kernel<<<(DM * DM / 4) / 256, 256>>>(W_dt);
    split_wbc_kernel<<<32, 256>>>(W_B, W_C);
    gemm_mma_kernel<<<dim3(DM / 128, MTOT / 128), 256, GSMEM>>>(b_dt);
    bc_mma_kernel<<<MTOT / 64, 128>>>(b_B, b_C);
    transpose_delta_kernel<<<dim3(DM / 32, SEQ / 32, BATCH), dim3(32, 8)>>>();
    scan_pass1<<<dim3(DM / 16, CH, BATCH), 128>>>(logA);
    scan_combine<<<(BATCH * DM * DS) / 256, 256>>>();
    scan_pass3<<<dim3(DM / 16, CH, BATCH), 128>>>(logA);
    out_kernel<<<dim3(SEQ / 32, DM / 32, BATCH), dim3(32, 8)>>>(x, Dsk, out);
}